// round 2
// baseline (speedup 1.0000x reference)
#include <cuda_runtime.h>

// ---------------------------------------------------------------------------
// StockLSTM: 2-layer LSTM (B=4096, T=256, I=5, H=64) + FC(64->25)
// Persistent-block SIMT design:
//   - each block owns NB=4 batch elements, runs full T recurrence for both
//     layers locally (no cross-block sync needed).
//   - thread = (batch_local, cell j); computes gates i,f,g,o for its cell.
//   - all weights staged in SMEM, pre-interleaved by a prep kernel into
//     k-pair / gate-pair layout so the inner loop is:
//        LDS.128 (Wi,Wi',Wf,Wf') + LDS.128 (Wg,Wg',Wo,Wo') + LDS.64 (h,h')
//        + 4x fma.rn.f32x2        (2 MACs per op -> 128 MAC/cyc/SM)
//   - weight tables use 16B entries with 16B lane stride => conflict-free;
//     h reads are warp-uniform => broadcast.
// ---------------------------------------------------------------------------

#define B_      4096
#define T_      256
#define I_      5
#define H_      64
#define O_      25
#define NB      4          // batch elems per block
#define THREADS 256
#define KP_H    32         // 64 k values -> 32 pairs
#define KP_X    3          // 5 (+1 zero pad) -> 3 pairs

typedef unsigned long long ull;

// ---- prepped (interleaved) weights in static device scratch ---------------
__device__ float4 gA0h[KP_H * H_];   // layer0 Whh, gates (i,f)
__device__ float4 gB0h[KP_H * H_];   // layer0 Whh, gates (g,o)
__device__ float4 gA0x[KP_X * H_];   // layer0 Wih (K=5 padded to 6)
__device__ float4 gB0x[KP_X * H_];
__device__ float4 gA1x[KP_H * H_];   // layer1 Wih (input = h1)
__device__ float4 gB1x[KP_H * H_];
__device__ float4 gA1h[KP_H * H_];   // layer1 Whh
__device__ float4 gB1h[KP_H * H_];
__device__ float4 gBias0[H_];        // (bih+bhh) per gate
__device__ float4 gBias1[H_];

// ---------------------------------------------------------------------------
__global__ void prep_kernel(const float* __restrict__ Wih0, const float* __restrict__ Whh0,
                            const float* __restrict__ bih0, const float* __restrict__ bhh0,
                            const float* __restrict__ Wih1, const float* __restrict__ Whh1,
                            const float* __restrict__ bih1, const float* __restrict__ bhh1)
{
    const int stride = gridDim.x * blockDim.x;
    const int tid0   = blockIdx.x * blockDim.x + threadIdx.x;

    for (int idx = tid0; idx < KP_H * H_; idx += stride) {
        const int p  = idx >> 6;        // k-pair
        const int j  = idx & 63;        // cell
        const int k0 = 2 * p, k1 = k0 + 1;
        gA0h[idx] = make_float4(Whh0[j*H_+k0],        Whh0[j*H_+k1],
                                Whh0[(H_+j)*H_+k0],   Whh0[(H_+j)*H_+k1]);
        gB0h[idx] = make_float4(Whh0[(2*H_+j)*H_+k0], Whh0[(2*H_+j)*H_+k1],
                                Whh0[(3*H_+j)*H_+k0], Whh0[(3*H_+j)*H_+k1]);
        gA1x[idx] = make_float4(Wih1[j*H_+k0],        Wih1[j*H_+k1],
                                Wih1[(H_+j)*H_+k0],   Wih1[(H_+j)*H_+k1]);
        gB1x[idx] = make_float4(Wih1[(2*H_+j)*H_+k0], Wih1[(2*H_+j)*H_+k1],
                                Wih1[(3*H_+j)*H_+k0], Wih1[(3*H_+j)*H_+k1]);
        gA1h[idx] = make_float4(Whh1[j*H_+k0],        Whh1[j*H_+k1],
                                Whh1[(H_+j)*H_+k0],   Whh1[(H_+j)*H_+k1]);
        gB1h[idx] = make_float4(Whh1[(2*H_+j)*H_+k0], Whh1[(2*H_+j)*H_+k1],
                                Whh1[(3*H_+j)*H_+k0], Whh1[(3*H_+j)*H_+k1]);
    }
    for (int idx = tid0; idx < KP_X * H_; idx += stride) {
        const int p  = idx >> 6;
        const int j  = idx & 63;
        const int k0 = 2 * p, k1 = k0 + 1;
        const bool k1ok = (k1 < I_);
        gA0x[idx] = make_float4(Wih0[j*I_+k0],        k1ok ? Wih0[j*I_+k1]        : 0.f,
                                Wih0[(H_+j)*I_+k0],   k1ok ? Wih0[(H_+j)*I_+k1]   : 0.f);
        gB0x[idx] = make_float4(Wih0[(2*H_+j)*I_+k0], k1ok ? Wih0[(2*H_+j)*I_+k1] : 0.f,
                                Wih0[(3*H_+j)*I_+k0], k1ok ? Wih0[(3*H_+j)*I_+k1] : 0.f);
    }
    for (int j = tid0; j < H_; j += stride) {
        gBias0[j] = make_float4(bih0[j]      + bhh0[j],
                                bih0[H_+j]   + bhh0[H_+j],
                                bih0[2*H_+j] + bhh0[2*H_+j],
                                bih0[3*H_+j] + bhh0[3*H_+j]);
        gBias1[j] = make_float4(bih1[j]      + bhh1[j],
                                bih1[H_+j]   + bhh1[H_+j],
                                bih1[2*H_+j] + bhh1[2*H_+j],
                                bih1[3*H_+j] + bhh1[3*H_+j]);
    }
}

// ---- packed f32x2 helpers -------------------------------------------------
__device__ __forceinline__ ull pack2(float lo, float hi) {
    ull r; asm("mov.b64 %0, {%1, %2};" : "=l"(r) : "f"(lo), "f"(hi)); return r;
}
__device__ __forceinline__ float red2(ull v) {
    float lo, hi; asm("mov.b64 {%0, %1}, %2;" : "=f"(lo), "=f"(hi) : "l"(v)); return lo + hi;
}
__device__ __forceinline__ void fma2(ull& d, ull a, ull b) {
    asm("fma.rn.f32x2 %0, %1, %2, %3;" : "=l"(d) : "l"(a), "l"(b), "l"(d));
}
__device__ __forceinline__ float sigm(float v)  { return __fdividef(1.f, 1.f + __expf(-v)); }
__device__ __forceinline__ float tanh_f(float v){ return __fdividef(2.f, 1.f + __expf(-2.f * v)) - 1.f; }

// Accumulate NP k-pairs of the gate matvec for cell j.
template<int NP>
__device__ __forceinline__ void mv(ull& ai, ull& af, ull& ag, ull& ao,
                                   const float4* __restrict__ A,
                                   const float4* __restrict__ Bv,
                                   const float* __restrict__ hsrc, int j)
{
#pragma unroll
    for (int p = 0; p < NP; ++p) {
        const ulonglong2 wa = *reinterpret_cast<const ulonglong2*>(A  + p * H_ + j);
        const ulonglong2 wb = *reinterpret_cast<const ulonglong2*>(Bv + p * H_ + j);
        const ull        hv = *reinterpret_cast<const ull*>(hsrc + 2 * p);  // warp-uniform -> broadcast
        fma2(ai, wa.x, hv);
        fma2(af, wa.y, hv);
        fma2(ag, wb.x, hv);
        fma2(ao, wb.y, hv);
    }
}

// SMEM layout (float4 units)
#define SM_TOTAL_BYTES 231424

__global__ __launch_bounds__(THREADS)
void lstm_kernel(const float* __restrict__ x,
                 const float* __restrict__ Wfc, const float* __restrict__ bfc,
                 float* __restrict__ out)
{
    extern __shared__ float4 smem[];
    float4* sA0h = smem;             // 2048
    float4* sB0h = smem + 2048;      // 2048
    float4* sA1x = smem + 4096;      // 2048
    float4* sB1x = smem + 6144;      // 2048
    float4* sA1h = smem + 8192;      // 2048
    float4* sB1h = smem + 10240;     // 2048
    float4* sA0x = smem + 12288;     // 192
    float4* sB0x = smem + 12480;     // 192
    float4* sb0  = smem + 12672;     // 64
    float4* sb1  = smem + 12736;     // 64
    float*  sf   = reinterpret_cast<float*>(smem + 12800);
    float*  sx   = sf;               // NB*T*6 = 6144 floats (x padded to 6/step)
    float*  sh1  = sf + 6144;        // 256
    float*  sh2  = sf + 6400;        // 256

    const int tid = threadIdx.x;
    const int b0  = blockIdx.x * NB;

    // ---- stage weights (coalesced float4 copies; L2-resident) ----
    for (int i = tid; i < 2048; i += THREADS) {
        sA0h[i] = gA0h[i]; sB0h[i] = gB0h[i];
        sA1x[i] = gA1x[i]; sB1x[i] = gB1x[i];
        sA1h[i] = gA1h[i]; sB1h[i] = gB1h[i];
    }
    if (tid < 192) { sA0x[tid] = gA0x[tid]; sB0x[tid] = gB0x[tid]; }
    if (tid < 64)  { sb0[tid]  = gBias0[tid]; sb1[tid] = gBias1[tid]; }

    // ---- stage x tile: [NB][T][5] -> padded stride 6 (keeps pairs 8B aligned) ----
    for (int i = tid; i < NB * T_ * I_; i += THREADS) {
        const int bl = i / (T_ * I_);
        const int r  = i - bl * (T_ * I_);
        const int t  = r / I_;
        const int c  = r - t * I_;
        sx[bl * (T_ * 6) + t * 6 + c] = x[(size_t)(b0 + bl) * (T_ * I_) + r];
    }
    for (int i = tid; i < NB * T_; i += THREADS) {
        const int bl = i / T_, t = i - bl * T_;
        sx[bl * (T_ * 6) + t * 6 + 5] = 0.f;
    }
    sh1[tid] = 0.f;
    sh2[tid] = 0.f;
    __syncthreads();

    const int bl = tid >> 6;         // local batch elem (warp-uniform)
    const int j  = tid & 63;         // cell
    const float* my_sh1 = sh1 + bl * H_;
    const float* my_sh2 = sh2 + bl * H_;
    const float* my_sx  = sx  + bl * (T_ * 6);
    const float4 bv0 = sb0[j];
    const float4 bv1 = sb1[j];
    float c1 = 0.f, c2 = 0.f;

#pragma unroll 1
    for (int t = 0; t < T_; ++t) {
        // ---------------- layer 0 ----------------
        ull ai = pack2(bv0.x, 0.f), af = pack2(bv0.y, 0.f);
        ull ag = pack2(bv0.z, 0.f), ao = pack2(bv0.w, 0.f);
        mv<KP_H>(ai, af, ag, ao, sA0h, sB0h, my_sh1, j);
        mv<KP_X>(ai, af, ag, ao, sA0x, sB0x, my_sx + t * 6, j);
        {
            const float iv = sigm(red2(ai));
            const float fv = sigm(red2(af));
            const float gv = tanh_f(red2(ag));
            const float ov = sigm(red2(ao));
            c1 = fv * c1 + iv * gv;
            const float h1n = ov * tanh_f(c1);
            __syncthreads();             // all reads of sh1(t-1) done
            sh1[tid] = h1n;              // publish h1(t)
            __syncthreads();
        }
        // ---------------- layer 1 ----------------
        ai = pack2(bv1.x, 0.f); af = pack2(bv1.y, 0.f);
        ag = pack2(bv1.z, 0.f); ao = pack2(bv1.w, 0.f);
        mv<KP_H>(ai, af, ag, ao, sA1x, sB1x, my_sh1, j);   // input  = h1(t)
        mv<KP_H>(ai, af, ag, ao, sA1h, sB1h, my_sh2, j);   // recur  = h2(t-1)
        {
            const float iv = sigm(red2(ai));
            const float fv = sigm(red2(af));
            const float gv = tanh_f(red2(ag));
            const float ov = sigm(red2(ao));
            c2 = fv * c2 + iv * gv;
            const float h2n = ov * tanh_f(c2);
            __syncthreads();             // all reads of sh2(t-1) done
            sh2[tid] = h2n;              // publish h2(t)
            __syncthreads();
        }
    }

    // ---------------- FC on h2(T-1) ----------------
    for (int i = tid; i < NB * O_; i += THREADS) {
        const int bb = i / O_;
        const int o  = i - bb * O_;
        const float* hrow = sh2 + bb * H_;
        const float* wrow = Wfc + o * H_;
        float acc = bfc[o];
#pragma unroll
        for (int k = 0; k < H_; ++k) acc += hrow[k] * wrow[k];
        out[(b0 + bb) * O_ + o] = acc;
    }
}

// ---------------------------------------------------------------------------
extern "C" void kernel_launch(void* const* d_in, const int* in_sizes, int n_in,
                              void* d_out, int out_size)
{
    (void)in_sizes; (void)n_in; (void)out_size;
    const float* x    = (const float*)d_in[0];
    const float* Wih0 = (const float*)d_in[1];
    const float* Whh0 = (const float*)d_in[2];
    const float* bih0 = (const float*)d_in[3];
    const float* bhh0 = (const float*)d_in[4];
    const float* Wih1 = (const float*)d_in[5];
    const float* Whh1 = (const float*)d_in[6];
    const float* bih1 = (const float*)d_in[7];
    const float* bhh1 = (const float*)d_in[8];
    const float* Wfc  = (const float*)d_in[9];
    const float* bfc  = (const float*)d_in[10];
    float* out = (float*)d_out;

    cudaFuncSetAttribute(lstm_kernel, cudaFuncAttributeMaxDynamicSharedMemorySize,
                         SM_TOTAL_BYTES);

    prep_kernel<<<32, 256>>>(Wih0, Whh0, bih0, bhh0, Wih1, Whh1, bih1, bhh1);
    lstm_kernel<<<B_ / NB, THREADS, SM_TOTAL_BYTES>>>(x, Wfc, bfc, out);
}

// round 8
// speedup vs baseline: 4.9638x; 4.9638x over previous
#include <cuda_runtime.h>

// ---------------------------------------------------------------------------
// StockLSTM: batch-vectorized packed-f32x2 persistent LSTM.
//   block = 256 thr = 4 independent groups of 64; group = all 64 cells for
//   8 batch elements (4 batch-pairs). Weights float4[k][j]=(wi,wf,wg,wo) in
//   SMEM; per k: 1 LDS.128 + 4 dup + 4 broadcast LDS.64 + 16 fma.rn.f32x2.
//   Each weight load feeds 8 batch elements -> FMA-bound, not LDS-bound.
//   R7 fix: sW0x staging loop covered only 256/320 entries (k=4 column of
//   Wih0 was garbage) -> strided copy loop.
// ---------------------------------------------------------------------------

#define B_      4096
#define T_      256
#define I_      5
#define H_      64
#define O_      25
#define NBT     8          // batch elems per group
#define BP      4          // batch pairs per group
#define GROUPS  4
#define THREADS 256
#define TCH     4          // x chunk (timesteps)

typedef unsigned long long ull;

// ---- prepped weights: float4[k*64+j] = (w_i, w_f, w_g, w_o) ---------------
__device__ float4 gW0h[H_ * H_];     // layer0 Whh
__device__ float4 gW1x[H_ * H_];     // layer1 Wih
__device__ float4 gW1h[H_ * H_];     // layer1 Whh
__device__ float4 gW0x[I_ * H_];     // layer0 Wih  (k = 0..4)
__device__ float4 gBias0[H_];
__device__ float4 gBias1[H_];

__global__ void prep_kernel(const float* __restrict__ Wih0, const float* __restrict__ Whh0,
                            const float* __restrict__ bih0, const float* __restrict__ bhh0,
                            const float* __restrict__ Wih1, const float* __restrict__ Whh1,
                            const float* __restrict__ bih1, const float* __restrict__ bhh1)
{
    const int stride = gridDim.x * blockDim.x;
    const int tid0   = blockIdx.x * blockDim.x + threadIdx.x;

    for (int idx = tid0; idx < H_ * H_; idx += stride) {
        const int k = idx >> 6, j = idx & 63;
        gW0h[idx] = make_float4(Whh0[j*H_+k],        Whh0[(H_+j)*H_+k],
                                Whh0[(2*H_+j)*H_+k], Whh0[(3*H_+j)*H_+k]);
        gW1x[idx] = make_float4(Wih1[j*H_+k],        Wih1[(H_+j)*H_+k],
                                Wih1[(2*H_+j)*H_+k], Wih1[(3*H_+j)*H_+k]);
        gW1h[idx] = make_float4(Whh1[j*H_+k],        Whh1[(H_+j)*H_+k],
                                Whh1[(2*H_+j)*H_+k], Whh1[(3*H_+j)*H_+k]);
    }
    for (int idx = tid0; idx < I_ * H_; idx += stride) {
        const int k = idx >> 6, j = idx & 63;
        gW0x[idx] = make_float4(Wih0[j*I_+k],        Wih0[(H_+j)*I_+k],
                                Wih0[(2*H_+j)*I_+k], Wih0[(3*H_+j)*I_+k]);
    }
    for (int j = tid0; j < H_; j += stride) {
        gBias0[j] = make_float4(bih0[j]      + bhh0[j],
                                bih0[H_+j]   + bhh0[H_+j],
                                bih0[2*H_+j] + bhh0[2*H_+j],
                                bih0[3*H_+j] + bhh0[3*H_+j]);
        gBias1[j] = make_float4(bih1[j]      + bhh1[j],
                                bih1[H_+j]   + bhh1[H_+j],
                                bih1[2*H_+j] + bhh1[2*H_+j],
                                bih1[3*H_+j] + bhh1[3*H_+j]);
    }
}

// ---- packed helpers -------------------------------------------------------
__device__ __forceinline__ ull dup2(float v) {
    ull r; asm("mov.b64 %0, {%1, %1};" : "=l"(r) : "f"(v)); return r;
}
__device__ __forceinline__ void unpk(float& lo, float& hi, ull v) {
    asm("mov.b64 {%0, %1}, %2;" : "=f"(lo), "=f"(hi) : "l"(v));
}
__device__ __forceinline__ void fma2(ull& d, ull a, ull b) {
    asm("fma.rn.f32x2 %0, %1, %2, %3;" : "=l"(d) : "l"(a), "l"(b), "l"(d));
}
__device__ __forceinline__ float sigm(float v)   { return __fdividef(1.f, 1.f + __expf(-v)); }
__device__ __forceinline__ float tanh_f(float v) { return __fdividef(2.f, 1.f + __expf(-2.f * v)) - 1.f; }
__device__ __forceinline__ void barg(int g) {
    asm volatile("bar.sync %0, 64;" :: "r"(1 + g) : "memory");
}

// SMEM: 3*64KB weights + 5KB W0x + 8KB h1 + 8KB h2 + 2.5KB x = 220672 B
#define SM_BYTES 220672

__global__ __launch_bounds__(THREADS)
void lstm_kernel(const float* __restrict__ x,
                 const float* __restrict__ Wfc, const float* __restrict__ bfc,
                 float* __restrict__ out)
{
    extern __shared__ float4 smem[];
    float4* sW0h = smem;                    // 4096 float4
    float4* sW1x = smem + 4096;             // 4096
    float4* sW1h = smem + 8192;             // 4096
    float4* sW0x = smem + 12288;            // 320
    float*  sf   = reinterpret_cast<float*>(smem + 12608);
    float*  h1T  = sf;                      // [4 grp][BP][64 k][2]  = 2048 f
    float*  h2T  = sf + 2048;               // 2048 f
    float*  sxT  = sf + 4096;               // [4 grp][BP][TCH*5][2] = 640 f

    const int tid = threadIdx.x;

    for (int i = tid; i < H_ * H_; i += THREADS) {
        sW0h[i] = gW0h[i]; sW1x[i] = gW1x[i]; sW1h[i] = gW1h[i];
    }
    for (int i = tid; i < I_ * H_; i += THREADS)   // R7 FIX: was `if (tid < 320)` with 256 threads
        sW0x[i] = gW0x[i];
    for (int i = tid; i < 2048; i += THREADS) { h1T[i] = 0.f; h2T[i] = 0.f; }
    __syncthreads();

    const int g  = tid >> 6;                // group (warp-uniform)
    const int j  = tid & 63;                // cell / lane-in-group
    const int b0 = blockIdx.x * (GROUPS * NBT) + g * NBT;

    float* h1 = h1T + g * (BP * H_ * 2);    // [bp*128 + k*2 + e]
    float* h2 = h2T + g * (BP * H_ * 2);
    float* sx = sxT + g * (BP * TCH * I_ * 2);  // [bp*40 + (tt*5+kk)*2 + e]

    const float4 bv0 = gBias0[j];
    const float4 bv1 = gBias1[j];
    const ull bi0 = dup2(bv0.x), bf0 = dup2(bv0.y), bg0 = dup2(bv0.z), bo0 = dup2(bv0.w);
    const ull bi1 = dup2(bv1.x), bf1 = dup2(bv1.y), bg1 = dup2(bv1.z), bo1 = dup2(bv1.w);

    float c1[NBT], c2[NBT];
#pragma unroll
    for (int b = 0; b < NBT; ++b) { c1[b] = 0.f; c2[b] = 0.f; }

    ull ai[BP], af[BP], ag[BP], ao[BP];

#pragma unroll 1
    for (int t = 0; t < T_; ++t) {
        // ---- stage x chunk (group-local) ----
        if ((t & (TCH - 1)) == 0) {
            for (int i = j; i < NBT * TCH * I_; i += 64) {
                const int bl = i & 7;
                const int r  = i >> 3;          // 0..19 = tt*5+kk
                const int bp = bl >> 1, e = bl & 1;
                sx[bp * (TCH * I_ * 2) + r * 2 + e]
                    = x[(size_t)(b0 + bl) * (T_ * I_) + t * I_ + r];
            }
            barg(g);
        }

        // ================= layer 0 =================
#pragma unroll
        for (int bp = 0; bp < BP; ++bp) { ai[bp]=bi0; af[bp]=bf0; ag[bp]=bg0; ao[bp]=bo0; }
#pragma unroll 8
        for (int k = 0; k < H_; ++k) {
            const float4 w = sW0h[k * H_ + j];
            const ull wi = dup2(w.x), wf = dup2(w.y), wg = dup2(w.z), wo = dup2(w.w);
#pragma unroll
            for (int bp = 0; bp < BP; ++bp) {
                const ull hv = *reinterpret_cast<const ull*>(h1 + bp * 128 + k * 2);
                fma2(ai[bp], wi, hv); fma2(af[bp], wf, hv);
                fma2(ag[bp], wg, hv); fma2(ao[bp], wo, hv);
            }
        }
#pragma unroll
        for (int k = 0; k < I_; ++k) {
            const float4 w = sW0x[k * H_ + j];
            const ull wi = dup2(w.x), wf = dup2(w.y), wg = dup2(w.z), wo = dup2(w.w);
            const int xoff = ((t & (TCH - 1)) * I_ + k) * 2;
#pragma unroll
            for (int bp = 0; bp < BP; ++bp) {
                const ull xv = *reinterpret_cast<const ull*>(sx + bp * (TCH * I_ * 2) + xoff);
                fma2(ai[bp], wi, xv); fma2(af[bp], wf, xv);
                fma2(ag[bp], wg, xv); fma2(ao[bp], wo, xv);
            }
        }
        float h1v[NBT];
#pragma unroll
        for (int bp = 0; bp < BP; ++bp) {
            float i0,i1,f0,f1,g0,g1,o0,o1;
            unpk(i0,i1,ai[bp]); unpk(f0,f1,af[bp]); unpk(g0,g1,ag[bp]); unpk(o0,o1,ao[bp]);
            const float cA = sigm(f0)*c1[2*bp]   + sigm(i0)*tanh_f(g0);
            const float cB = sigm(f1)*c1[2*bp+1] + sigm(i1)*tanh_f(g1);
            c1[2*bp]   = cA; h1v[2*bp]   = sigm(o0)*tanh_f(cA);
            c1[2*bp+1] = cB; h1v[2*bp+1] = sigm(o1)*tanh_f(cB);
        }
        barg(g);                               // all reads of h1(t-1) done
#pragma unroll
        for (int bp = 0; bp < BP; ++bp)
            *reinterpret_cast<float2*>(h1 + bp * 128 + j * 2) = make_float2(h1v[2*bp], h1v[2*bp+1]);
        barg(g);                               // h1(t) visible

        // ================= layer 1 =================
#pragma unroll
        for (int bp = 0; bp < BP; ++bp) { ai[bp]=bi1; af[bp]=bf1; ag[bp]=bg1; ao[bp]=bo1; }
#pragma unroll 4
        for (int k = 0; k < H_; ++k) {
            const float4 wx = sW1x[k * H_ + j];
            const float4 wh = sW1h[k * H_ + j];
            const ull xi = dup2(wx.x), xf = dup2(wx.y), xg = dup2(wx.z), xo = dup2(wx.w);
            const ull hi = dup2(wh.x), hf = dup2(wh.y), hg = dup2(wh.z), ho = dup2(wh.w);
#pragma unroll
            for (int bp = 0; bp < BP; ++bp) {
                const ull xv = *reinterpret_cast<const ull*>(h1 + bp * 128 + k * 2);
                const ull hv = *reinterpret_cast<const ull*>(h2 + bp * 128 + k * 2);
                fma2(ai[bp], xi, xv); fma2(af[bp], xf, xv);
                fma2(ag[bp], xg, xv); fma2(ao[bp], xo, xv);
                fma2(ai[bp], hi, hv); fma2(af[bp], hf, hv);
                fma2(ag[bp], hg, hv); fma2(ao[bp], ho, hv);
            }
        }
        float h2v[NBT];
#pragma unroll
        for (int bp = 0; bp < BP; ++bp) {
            float i0,i1,f0,f1,g0,g1,o0,o1;
            unpk(i0,i1,ai[bp]); unpk(f0,f1,af[bp]); unpk(g0,g1,ag[bp]); unpk(o0,o1,ao[bp]);
            const float cA = sigm(f0)*c2[2*bp]   + sigm(i0)*tanh_f(g0);
            const float cB = sigm(f1)*c2[2*bp+1] + sigm(i1)*tanh_f(g1);
            c2[2*bp]   = cA; h2v[2*bp]   = sigm(o0)*tanh_f(cA);
            c2[2*bp+1] = cB; h2v[2*bp+1] = sigm(o1)*tanh_f(cB);
        }
        barg(g);                               // all reads of h2(t-1) done
#pragma unroll
        for (int bp = 0; bp < BP; ++bp)
            *reinterpret_cast<float2*>(h2 + bp * 128 + j * 2) = make_float2(h2v[2*bp], h2v[2*bp+1]);
        barg(g);                               // h2(t) visible
    }

    // ---- FC on h2(T-1): out[b][o] = sum_k h2[k][b] * Wfc[o][k] + bfc[o] ----
    for (int i = j; i < NBT * O_; i += 64) {
        const int bl = i / O_;
        const int o  = i - bl * O_;
        const int bp = bl >> 1, e = bl & 1;
        const float* wrow = Wfc + o * H_;
        float acc = bfc[o];
#pragma unroll 8
        for (int k = 0; k < H_; ++k)
            acc += h2[bp * 128 + k * 2 + e] * wrow[k];
        out[(size_t)(b0 + bl) * O_ + o] = acc;
    }
}

// ---------------------------------------------------------------------------
extern "C" void kernel_launch(void* const* d_in, const int* in_sizes, int n_in,
                              void* d_out, int out_size)
{
    (void)in_sizes; (void)n_in; (void)out_size;
    const float* x    = (const float*)d_in[0];
    const float* Wih0 = (const float*)d_in[1];
    const float* Whh0 = (const float*)d_in[2];
    const float* bih0 = (const float*)d_in[3];
    const float* bhh0 = (const float*)d_in[4];
    const float* Wih1 = (const float*)d_in[5];
    const float* Whh1 = (const float*)d_in[6];
    const float* bih1 = (const float*)d_in[7];
    const float* bhh1 = (const float*)d_in[8];
    const float* Wfc  = (const float*)d_in[9];
    const float* bfc  = (const float*)d_in[10];
    float* out = (float*)d_out;

    cudaFuncSetAttribute(lstm_kernel, cudaFuncAttributeMaxDynamicSharedMemorySize,
                         SM_BYTES);

    prep_kernel<<<32, 256>>>(Wih0, Whh0, bih0, bhh0, Wih1, Whh1, bih1, bhh1);
    lstm_kernel<<<B_ / (GROUPS * NBT), THREADS, SM_BYTES>>>(x, Wfc, bfc, out);
}